// round 15
// baseline (speedup 1.0000x reference)
#include <cuda_runtime.h>
#include <cuda_fp16.h>
#include <cstdint>

#define N_NODES 10000
#define N_EDGES 320000
#define IN_CH   256
#define OUT_CH  256
#define WPAD    320   // u32 words per bitmap row (need 313, pad to 320)

// Scratch (device globals; no allocation allowed)
__device__ unsigned g_bitmap[N_NODES * WPAD];            // 12.8 MB adjacency bitmap
__device__ int      g_deg[N_NODES];
__device__ __align__(16) __half g_xwh[N_NODES * OUT_CH]; // 5 MB: UNSCALED (X@W) fp16

// ---------------------------------------------------------------------------
// 1) zero bitmap (uint4) + diagonal self-loop bit, deg = 1
// ---------------------------------------------------------------------------
#define INIT_THREADS 256
#define INIT_BLOCKS  3125   // 3125*256 = 800000 = N_NODES*WPAD/4

__global__ void k_init() {
    int i = blockIdx.x * INIT_THREADS + threadIdx.x;   // uint4 index
    int row   = i / 80;            // 80 uint4 per row
    int widx4 = i - row * 80;
    uint4 z = make_uint4(0u, 0u, 0u, 0u);
    int dw = row >> 5;
    if ((dw >> 2) == widx4) {
        unsigned bit = 1u << (row & 31);
        switch (dw & 3) { case 0: z.x = bit; break; case 1: z.y = bit; break;
                          case 2: z.z = bit; break; default: z.w = bit; }
    }
    reinterpret_cast<uint4*>(g_bitmap)[i] = z;
    if (i < N_NODES) g_deg[i] = 1;
}

// ---------------------------------------------------------------------------
// 2) scatter edges; atomicOr return value dedupes degree counting
// ---------------------------------------------------------------------------
__global__ void k_scatter(const int* __restrict__ ei) {
    int e = blockIdx.x * blockDim.x + threadIdx.x;
    if (e >= N_EDGES) return;
    int src = ei[e];
    int dst = ei[N_EDGES + e];
    if ((unsigned)src >= N_NODES || (unsigned)dst >= N_NODES) return; // defensive
    unsigned bit = 1u << (dst & 31);
    unsigned old = atomicOr(&g_bitmap[src * WPAD + (dst >> 5)], bit);
    if (!(old & bit)) atomicAdd(&g_deg[src], 1);
}

// ---------------------------------------------------------------------------
// 3) TF32 tensor-core GEMM (UNSCALED) with MMA-fragment-permuted smem:
//    every fragment load is one LDS.128 instead of 4 LDS.32.
//
//    A permuted layout: value (m,k), m in [0,128), k in [0,16):
//      mb=m/16, q'=m%8, h=(m/8)&1, ks=k/8, half=(k%8)/4, rg=k%3? no: rg=k%4
//      slot s = half*2 + h  (orders the quad as (q,rg),(q+8,rg),(q,rg+4),(q+8,rg+4))
//      float idx = ((mb*2+ks)*32 + q'*4+rg)*4 + s
//    Fragment (warp wm, mt, ks, lane=q*4+rgrp): LDS.128 at
//      ((wm/16+mt)*2+ks)*128 + lane*4
//
//    B permuted layout (BSTR2=72 floats/row; 72/4=18 ≡ 2 mod 8 → .128 phases
//    conflict-free): value (k, c), c in [0,64):
//      float idx = k*72 + (c/32)*32 + (c%8)*4 + ((c/8)%4)
//    Fragment (k-row kr, warp wn, lane): LDS.128 at kr*72 + wn + q*4
//      gives {nt=0..3}; rows kr=kb+rgrp and kb+rgrp+4 give the b0/b1 halves.
// ---------------------------------------------------------------------------
#define BM 128
#define BN 64
#define BK 16
#define NTILES (IN_CH / BK)   // 16
#define BSTR2 72

__device__ __forceinline__ uint32_t to_tf32(float x) {
    uint32_t r;
    asm("cvt.rna.tf32.f32 %0, %1;" : "=r"(r) : "f"(x));
    return r;
}

__device__ __forceinline__ void mma_tf32(float* d, const uint32_t* a, const uint32_t* b) {
    asm volatile(
        "mma.sync.aligned.m16n8k8.row.col.f32.tf32.tf32.f32 "
        "{%0,%1,%2,%3}, {%4,%5,%6,%7}, {%8,%9}, {%0,%1,%2,%3};"
        : "+f"(d[0]), "+f"(d[1]), "+f"(d[2]), "+f"(d[3])
        : "r"(a[0]), "r"(a[1]), "r"(a[2]), "r"(a[3]), "r"(b[0]), "r"(b[1]));
}

__global__ __launch_bounds__(256) void k_gemm(const float* __restrict__ x,
                                              const float* __restrict__ w) {
    __shared__ __align__(16) uint32_t As2[2][BM * BK];        // 2 x 8192 B
    __shared__ __align__(16) uint32_t Bs2[2][BK * BSTR2];     // 2 x 4608 B

    int tid  = threadIdx.x;
    int lane = tid & 31;
    int wid  = tid >> 5;
    int wm   = (wid & 3) * 32;
    int wn   = (wid >> 2) * 32;
    int q    = lane >> 2;
    int rgrp = lane & 3;

    int rowBase = blockIdx.y * BM;
    int colBase = blockIdx.x * BN;

    float acc[2][4][4];
    #pragma unroll
    for (int i = 0; i < 2; i++)
        #pragma unroll
        for (int j = 0; j < 4; j++)
            #pragma unroll
            for (int k = 0; k < 4; k++) acc[i][j][k] = 0.0f;

    float4 aR[2], bR;

    auto loadGlobal = [&](int k0) {
        #pragma unroll
        for (int r = 0; r < 2; r++) {
            int lin  = tid + 256 * r;
            int grow = rowBase + (lin >> 2);
            int cq   = (lin & 3) * 4;
            aR[r] = (grow < N_NODES)
                  ? *reinterpret_cast<const float4*>(&x[grow * IN_CH + k0 + cq])
                  : make_float4(0.f, 0.f, 0.f, 0.f);
        }
        int kk = tid >> 4;
        int cq = (tid & 15) * 4;
        bR = *reinterpret_cast<const float4*>(&w[(k0 + kk) * OUT_CH + colBase + cq]);
    };
    auto storeSmem = [&](int buf) {
        #pragma unroll
        for (int r = 0; r < 2; r++) {
            int lin = tid + 256 * r;
            int m   = lin >> 2;
            int cq  = (lin & 3) * 4;            // k base (multiple of 4)
            int mb  = m >> 4;
            int qp  = m & 7;
            int h   = (m >> 3) & 1;
            int ks  = cq >> 3;
            int half= (cq >> 2) & 1;
            int s   = half * 2 + h;
            int base = ((mb * 2 + ks) * 32 + qp * 4) * 4 + s;  // + rg*4 per j
            float v[4] = {aR[r].x, aR[r].y, aR[r].z, aR[r].w};
            #pragma unroll
            for (int j = 0; j < 4; j++)
                As2[buf][base + j * 4] = to_tf32(v[j]);
        }
        int kk = tid >> 4;
        int cq = (tid & 15) * 4;
        float v[4] = {bR.x, bR.y, bR.z, bR.w};
        #pragma unroll
        for (int j = 0; j < 4; j++) {
            int c = cq + j;
            int idx = kk * BSTR2 + (c >> 5) * 32 + (c & 7) * 4 + ((c >> 3) & 3);
            Bs2[buf][idx] = to_tf32(v[j]);
        }
    };

    loadGlobal(0);
    storeSmem(0);
    __syncthreads();

    int cur = 0;
    for (int t = 0; t < NTILES; t++) {
        if (t + 1 < NTILES) loadGlobal((t + 1) * BK);

        #pragma unroll
        for (int ks = 0; ks < 2; ks++) {
            int kb = ks * 8;
            // A fragments: one LDS.128 per mt
            uint4 a128[2];
            #pragma unroll
            for (int mt = 0; mt < 2; mt++) {
                int base = (((wm >> 4) + mt) * 2 + ks) * 128 + lane * 4;
                a128[mt] = *reinterpret_cast<const uint4*>(&As2[cur][base]);
            }
            // B fragments: two LDS.128 give {nt0..3} x {b0,b1}
            int bbase = (kb + rgrp) * BSTR2 + wn + q * 4;
            uint4 blo = *reinterpret_cast<const uint4*>(&Bs2[cur][bbase]);
            uint4 bhi = *reinterpret_cast<const uint4*>(&Bs2[cur][bbase + 4 * BSTR2]);
            const uint32_t* blo4 = reinterpret_cast<const uint32_t*>(&blo);
            const uint32_t* bhi4 = reinterpret_cast<const uint32_t*>(&bhi);

            #pragma unroll
            for (int mt = 0; mt < 2; mt++) {
                const uint32_t* afr = reinterpret_cast<const uint32_t*>(&a128[mt]);
                #pragma unroll
                for (int nt = 0; nt < 4; nt++) {
                    uint32_t bb[2] = {blo4[nt], bhi4[nt]};
                    mma_tf32(acc[mt][nt], afr, bb);
                }
            }
        }

        if (t + 1 < NTILES) {
            int nxt = cur ^ 1;
            storeSmem(nxt);
            __syncthreads();
            cur = nxt;
        }
    }

    // epilogue: pack UNSCALED column pairs into half2
    #pragma unroll
    for (int mt = 0; mt < 2; mt++) {
        int r0 = rowBase + wm + mt * 16 + q;
        int r1 = r0 + 8;
        #pragma unroll
        for (int nt = 0; nt < 4; nt++) {
            int c = colBase + wn + nt * 8 + rgrp * 2;
            if (r0 < N_NODES) {
                __half2 h = __floats2half2_rn(acc[mt][nt][0], acc[mt][nt][1]);
                *reinterpret_cast<__half2*>(&g_xwh[r0 * OUT_CH + c]) = h;
            }
            if (r1 < N_NODES) {
                __half2 h = __floats2half2_rn(acc[mt][nt][2], acc[mt][nt][3]);
                *reinterpret_cast<__half2*>(&g_xwh[r1 * OUT_CH + c]) = h;
            }
        }
    }
}

// ---------------------------------------------------------------------------
// 3b) scale rows by rsqrt(deg): 2 uint4 per thread (same row -> one rsqrt).
//     160000 threads -> 625 blocks.
// ---------------------------------------------------------------------------
__global__ __launch_bounds__(256) void k_scale() {
    int t = blockIdx.x * 256 + threadIdx.x;
    int base = t * 2;                       // uint4 index (even -> pair same row)
    if (base >= N_NODES * OUT_CH / 8) return;
    int row = base >> 5;                    // 32 uint4 per row
    float dv = rsqrtf((float)g_deg[row]);
    uint4* p = reinterpret_cast<uint4*>(g_xwh) + base;
    uint4 v0 = p[0], v1 = p[1];
    uint4 vv[2] = {v0, v1};
    #pragma unroll
    for (int r = 0; r < 2; r++) {
        __half2* h = reinterpret_cast<__half2*>(&vv[r]);
        #pragma unroll
        for (int i = 0; i < 4; i++) {
            float2 f = __half22float2(h[i]);
            h[i] = __floats2half2_rn(f.x * dv, f.y * dv);
        }
    }
    p[0] = vv[0]; p[1] = vv[1];
}

// ---------------------------------------------------------------------------
// 4) aggregate, warp-per-row over fp16 rows, 4-way HADD2 tree (R13 version).
// ---------------------------------------------------------------------------
#define AGG_WARPS 8
#define MAXDEG    128

__device__ __forceinline__ void add8(float* a, const uint4& v) {
    const __half2* h = reinterpret_cast<const __half2*>(&v);
    #pragma unroll
    for (int i = 0; i < 4; i++) {
        float2 f = __half22float2(h[i]);
        a[2 * i]     += f.x;
        a[2 * i + 1] += f.y;
    }
}

__global__ __launch_bounds__(256) void k_aggregate(float* __restrict__ out) {
    __shared__ int slist[AGG_WARPS][MAXDEG];

    int lane = threadIdx.x & 31;
    int wid  = threadIdx.x >> 5;
    int row  = blockIdx.x * AGG_WARPS + wid;   // grid*8 = 10000 exactly

    const unsigned* rowp = g_bitmap + row * WPAD;

    unsigned wv[10];
    int myc = 0;
    #pragma unroll
    for (int k = 0; k < 10; k++) {
        wv[k] = rowp[lane + 32 * k];
        myc += __popc(wv[k]);
    }

    int inc = myc;
    #pragma unroll
    for (int o = 1; o < 32; o <<= 1) {
        int v = __shfl_up_sync(0xffffffffu, inc, o);
        if (lane >= o) inc += v;
    }
    int deg = __shfl_sync(0xffffffffu, inc, 31);   // true degree (incl. self-loop)
    int off = inc - myc;

    #pragma unroll
    for (int k = 0; k < 10; k++) {
        unsigned w = wv[k];
        int base = (lane + 32 * k) << 5;
        while (w) {
            int b = __ffs(w) - 1;
            w &= w - 1;
            if (off < MAXDEG) slist[wid][off++] = base + b;
        }
    }
    __syncwarp();

    int cnt = deg > MAXDEG ? MAXDEG : deg;

    const uint4* xwh = reinterpret_cast<const uint4*>(g_xwh);  // 32 uint4 per row
    float acc[8] = {0.f, 0.f, 0.f, 0.f, 0.f, 0.f, 0.f, 0.f};

    int n = 0;
    for (; n + 3 < cnt; n += 4) {
        int j0 = slist[wid][n],     j1 = slist[wid][n + 1];
        int j2 = slist[wid][n + 2], j3 = slist[wid][n + 3];
        uint4 va = xwh[j0 * 32 + lane];
        uint4 vb = xwh[j1 * 32 + lane];
        uint4 vc = xwh[j2 * 32 + lane];
        uint4 vd = xwh[j3 * 32 + lane];
        const __half2* ha = reinterpret_cast<const __half2*>(&va);
        const __half2* hb = reinterpret_cast<const __half2*>(&vb);
        const __half2* hc = reinterpret_cast<const __half2*>(&vc);
        const __half2* hd = reinterpret_cast<const __half2*>(&vd);
        #pragma unroll
        for (int i = 0; i < 4; i++) {
            __half2 s01 = __hadd2(ha[i], hb[i]);
            __half2 s23 = __hadd2(hc[i], hd[i]);
            __half2 s   = __hadd2(s01, s23);
            float2 f = __half22float2(s);
            acc[2 * i]     += f.x;
            acc[2 * i + 1] += f.y;
        }
    }
    if (n + 1 < cnt) {
        int j0 = slist[wid][n], j1 = slist[wid][n + 1];
        uint4 va = xwh[j0 * 32 + lane];
        uint4 vb = xwh[j1 * 32 + lane];
        const __half2* ha = reinterpret_cast<const __half2*>(&va);
        const __half2* hb = reinterpret_cast<const __half2*>(&vb);
        #pragma unroll
        for (int i = 0; i < 4; i++) {
            __half2 s = __hadd2(ha[i], hb[i]);
            float2 f = __half22float2(s);
            acc[2 * i]     += f.x;
            acc[2 * i + 1] += f.y;
        }
        n += 2;
    }
    if (n < cnt) {
        uint4 v = xwh[slist[wid][n] * 32 + lane];
        add8(acc, v);
    }

    float dv = rsqrtf((float)deg);
    float4 r0 = make_float4(dv * acc[0], dv * acc[1], dv * acc[2], dv * acc[3]);
    float4 r1 = make_float4(dv * acc[4], dv * acc[5], dv * acc[6], dv * acc[7]);
    float4* out4 = reinterpret_cast<float4*>(out + row * OUT_CH);
    out4[lane * 2]     = r0;
    out4[lane * 2 + 1] = r1;
}

// ---------------------------------------------------------------------------
// Launch: fork-join graph.
//   stream 0 : init -> scatter ----\
//   stream B : gemm (x,w only) -----+--> scale -> aggregate
// ---------------------------------------------------------------------------
extern "C" void kernel_launch(void* const* d_in, const int* in_sizes, int n_in,
                              void* d_out, int out_size) {
    const float* x  = (const float*)d_in[0];   // [10000, 256] f32
    const float* w  = (const float*)d_in[1];   // [256, 256]   f32
    const int*   ei = (const int*)d_in[2];     // [2, 320000]  i32
    float* out = (float*)d_out;                // [10000, 256] f32

    cudaStream_t sB;
    cudaEvent_t evRoot, evGemm;
    cudaStreamCreateWithFlags(&sB, cudaStreamNonBlocking);
    cudaEventCreateWithFlags(&evRoot, cudaEventDisableTiming);
    cudaEventCreateWithFlags(&evGemm, cudaEventDisableTiming);

    cudaEventRecord(evRoot, 0);
    cudaStreamWaitEvent(sB, evRoot, 0);

    dim3 ggrid(OUT_CH / BN, (N_NODES + BM - 1) / BM);   // (4, 79) = 316 blocks
    k_gemm<<<ggrid, 256, 0, sB>>>(x, w);
    cudaEventRecord(evGemm, sB);

    k_init<<<INIT_BLOCKS, INIT_THREADS>>>();
    k_scatter<<<(N_EDGES + 255) / 256, 256>>>(ei);

    cudaStreamWaitEvent(0, evGemm, 0);
    k_scale<<<(N_NODES * OUT_CH / 8 / 2 + 255) / 256, 256>>>();   // 625 blocks
    k_aggregate<<<N_NODES / AGG_WARPS, 256>>>(out);
}

// round 16
// speedup vs baseline: 1.1775x; 1.1775x over previous
#include <cuda_runtime.h>
#include <cuda_fp16.h>
#include <cstdint>

#define N_NODES 10000
#define N_EDGES 320000
#define IN_CH   256
#define OUT_CH  256
#define WPAD    320   // u32 words per bitmap row (need 313, pad to 320)

// Scratch (device globals; no allocation allowed)
__device__ unsigned g_bitmap[N_NODES * WPAD];            // 12.8 MB adjacency bitmap
__device__ int      g_deg[N_NODES];
__device__ __align__(16) __half g_xwh[N_NODES * OUT_CH]; // 5 MB: UNSCALED (X@W) fp16

// ---------------------------------------------------------------------------
// 1) zero bitmap (uint4) + diagonal self-loop bit, deg = 1
// ---------------------------------------------------------------------------
#define INIT_THREADS 256
#define INIT_BLOCKS  3125   // 3125*256 = 800000 = N_NODES*WPAD/4

__global__ void k_init() {
    int i = blockIdx.x * INIT_THREADS + threadIdx.x;   // uint4 index
    int row   = i / 80;            // 80 uint4 per row
    int widx4 = i - row * 80;
    uint4 z = make_uint4(0u, 0u, 0u, 0u);
    int dw = row >> 5;
    if ((dw >> 2) == widx4) {
        unsigned bit = 1u << (row & 31);
        switch (dw & 3) { case 0: z.x = bit; break; case 1: z.y = bit; break;
                          case 2: z.z = bit; break; default: z.w = bit; }
    }
    reinterpret_cast<uint4*>(g_bitmap)[i] = z;
    if (i < N_NODES) g_deg[i] = 1;
}

// ---------------------------------------------------------------------------
// 2) scatter edges; atomicOr return value dedupes degree counting
// ---------------------------------------------------------------------------
__global__ void k_scatter(const int* __restrict__ ei) {
    int e = blockIdx.x * blockDim.x + threadIdx.x;
    if (e >= N_EDGES) return;
    int src = ei[e];
    int dst = ei[N_EDGES + e];
    if ((unsigned)src >= N_NODES || (unsigned)dst >= N_NODES) return; // defensive
    unsigned bit = 1u << (dst & 31);
    unsigned old = atomicOr(&g_bitmap[src * WPAD + (dst >> 5)], bit);
    if (!(old & bit)) atomicAdd(&g_deg[src], 1);
}

// ---------------------------------------------------------------------------
// 3) TF32 tensor-core GEMM (UNSCALED) — exact R11 version (measured good).
//    BM=128, BN=64, BK=16; 256 threads = 8 warps (4 m x 2 n), warp tile 32x32.
// ---------------------------------------------------------------------------
#define BM 128
#define BN 64
#define BK 16
#define NTILES (IN_CH / BK)   // 16
#define ASTR 20
#define BSTR 72

__device__ __forceinline__ uint32_t to_tf32(float x) {
    uint32_t r;
    asm("cvt.rna.tf32.f32 %0, %1;" : "=r"(r) : "f"(x));
    return r;
}

__device__ __forceinline__ void mma_tf32(float* d, const uint32_t* a, const uint32_t* b) {
    asm volatile(
        "mma.sync.aligned.m16n8k8.row.col.f32.tf32.tf32.f32 "
        "{%0,%1,%2,%3}, {%4,%5,%6,%7}, {%8,%9}, {%0,%1,%2,%3};"
        : "+f"(d[0]), "+f"(d[1]), "+f"(d[2]), "+f"(d[3])
        : "r"(a[0]), "r"(a[1]), "r"(a[2]), "r"(a[3]), "r"(b[0]), "r"(b[1]));
}

__global__ __launch_bounds__(256) void k_gemm(const float* __restrict__ x,
                                              const float* __restrict__ w) {
    __shared__ uint32_t As[2][BM * ASTR];
    __shared__ uint32_t Bs[2][BK * BSTR];

    int tid  = threadIdx.x;
    int lane = tid & 31;
    int wid  = tid >> 5;
    int wm   = (wid & 3) * 32;
    int wn   = (wid >> 2) * 32;
    int q    = lane >> 2;
    int rgrp = lane & 3;

    int rowBase = blockIdx.y * BM;
    int colBase = blockIdx.x * BN;

    float acc[2][4][4];
    #pragma unroll
    for (int i = 0; i < 2; i++)
        #pragma unroll
        for (int j = 0; j < 4; j++)
            #pragma unroll
            for (int k = 0; k < 4; k++) acc[i][j][k] = 0.0f;

    float4 aR[2], bR;

    auto loadGlobal = [&](int k0) {
        #pragma unroll
        for (int r = 0; r < 2; r++) {
            int lin  = tid + 256 * r;
            int grow = rowBase + (lin >> 2);
            int cq   = (lin & 3) * 4;
            aR[r] = (grow < N_NODES)
                  ? *reinterpret_cast<const float4*>(&x[grow * IN_CH + k0 + cq])
                  : make_float4(0.f, 0.f, 0.f, 0.f);
        }
        int kk = tid >> 4;
        int cq = (tid & 15) * 4;
        bR = *reinterpret_cast<const float4*>(&w[(k0 + kk) * OUT_CH + colBase + cq]);
    };
    auto storeSmem = [&](int buf) {
        #pragma unroll
        for (int r = 0; r < 2; r++) {
            int lin = tid + 256 * r;
            int row = lin >> 2;
            int cq  = (lin & 3) * 4;
            uint32_t* p = &As[buf][row * ASTR + cq];
            p[0] = to_tf32(aR[r].x); p[1] = to_tf32(aR[r].y);
            p[2] = to_tf32(aR[r].z); p[3] = to_tf32(aR[r].w);
        }
        int kk = tid >> 4;
        int cq = (tid & 15) * 4;
        uint32_t* p = &Bs[buf][kk * BSTR + cq];
        p[0] = to_tf32(bR.x); p[1] = to_tf32(bR.y);
        p[2] = to_tf32(bR.z); p[3] = to_tf32(bR.w);
    };

    loadGlobal(0);
    storeSmem(0);
    __syncthreads();

    int cur = 0;
    for (int t = 0; t < NTILES; t++) {
        if (t + 1 < NTILES) loadGlobal((t + 1) * BK);

        #pragma unroll
        for (int ks = 0; ks < 2; ks++) {
            int kb = ks * 8;
            uint32_t afr[2][4], bfr[4][2];
            #pragma unroll
            for (int mt = 0; mt < 2; mt++) {
                const uint32_t* base = &As[cur][(wm + mt * 16 + q) * ASTR + kb + rgrp];
                afr[mt][0] = base[0];
                afr[mt][1] = base[8 * ASTR];
                afr[mt][2] = base[4];
                afr[mt][3] = base[8 * ASTR + 4];
            }
            #pragma unroll
            for (int nt = 0; nt < 4; nt++) {
                const uint32_t* base = &Bs[cur][(kb + rgrp) * BSTR + wn + nt * 8 + q];
                bfr[nt][0] = base[0];
                bfr[nt][1] = base[4 * BSTR];
            }
            #pragma unroll
            for (int mt = 0; mt < 2; mt++)
                #pragma unroll
                for (int nt = 0; nt < 4; nt++)
                    mma_tf32(acc[mt][nt], afr[mt], bfr[nt]);
        }

        if (t + 1 < NTILES) {
            int nxt = cur ^ 1;
            storeSmem(nxt);
            __syncthreads();
            cur = nxt;
        }
    }

    // epilogue: pack UNSCALED column pairs into half2
    #pragma unroll
    for (int mt = 0; mt < 2; mt++) {
        int r0 = rowBase + wm + mt * 16 + q;
        int r1 = r0 + 8;
        #pragma unroll
        for (int nt = 0; nt < 4; nt++) {
            int c = colBase + wn + nt * 8 + rgrp * 2;
            if (r0 < N_NODES) {
                __half2 h = __floats2half2_rn(acc[mt][nt][0], acc[mt][nt][1]);
                *reinterpret_cast<__half2*>(&g_xwh[r0 * OUT_CH + c]) = h;
            }
            if (r1 < N_NODES) {
                __half2 h = __floats2half2_rn(acc[mt][nt][2], acc[mt][nt][3]);
                *reinterpret_cast<__half2*>(&g_xwh[r1 * OUT_CH + c]) = h;
            }
        }
    }
}

// ---------------------------------------------------------------------------
// 3b) scale rows by rsqrt(deg) — exact R11 version (best measured: 5.76us).
//     1 uint4 per thread, 1250 blocks.
// ---------------------------------------------------------------------------
__global__ __launch_bounds__(256) void k_scale() {
    int idx = blockIdx.x * 256 + threadIdx.x;   // 1250 * 256 = 320000
    int row = idx >> 5;
    float dv = rsqrtf((float)g_deg[row]);
    uint4 v = reinterpret_cast<uint4*>(g_xwh)[idx];
    __half2* h = reinterpret_cast<__half2*>(&v);
    #pragma unroll
    for (int i = 0; i < 4; i++) {
        float2 f = __half22float2(h[i]);
        h[i] = __floats2half2_rn(f.x * dv, f.y * dv);
    }
    reinterpret_cast<uint4*>(g_xwh)[idx] = v;
}

// ---------------------------------------------------------------------------
// 4) aggregate, warp-per-row over fp16 rows, 4-way HADD2 tree (R13 version,
//    measured ~1.3us faster than pair tree).
// ---------------------------------------------------------------------------
#define AGG_WARPS 8
#define MAXDEG    128

__device__ __forceinline__ void add8(float* a, const uint4& v) {
    const __half2* h = reinterpret_cast<const __half2*>(&v);
    #pragma unroll
    for (int i = 0; i < 4; i++) {
        float2 f = __half22float2(h[i]);
        a[2 * i]     += f.x;
        a[2 * i + 1] += f.y;
    }
}

__global__ __launch_bounds__(256) void k_aggregate(float* __restrict__ out) {
    __shared__ int slist[AGG_WARPS][MAXDEG];

    int lane = threadIdx.x & 31;
    int wid  = threadIdx.x >> 5;
    int row  = blockIdx.x * AGG_WARPS + wid;   // grid*8 = 10000 exactly

    const unsigned* rowp = g_bitmap + row * WPAD;

    unsigned wv[10];
    int myc = 0;
    #pragma unroll
    for (int k = 0; k < 10; k++) {
        wv[k] = rowp[lane + 32 * k];
        myc += __popc(wv[k]);
    }

    int inc = myc;
    #pragma unroll
    for (int o = 1; o < 32; o <<= 1) {
        int v = __shfl_up_sync(0xffffffffu, inc, o);
        if (lane >= o) inc += v;
    }
    int deg = __shfl_sync(0xffffffffu, inc, 31);   // true degree (incl. self-loop)
    int off = inc - myc;

    #pragma unroll
    for (int k = 0; k < 10; k++) {
        unsigned w = wv[k];
        int base = (lane + 32 * k) << 5;
        while (w) {
            int b = __ffs(w) - 1;
            w &= w - 1;
            if (off < MAXDEG) slist[wid][off++] = base + b;
        }
    }
    __syncwarp();

    int cnt = deg > MAXDEG ? MAXDEG : deg;

    const uint4* xwh = reinterpret_cast<const uint4*>(g_xwh);  // 32 uint4 per row
    float acc[8] = {0.f, 0.f, 0.f, 0.f, 0.f, 0.f, 0.f, 0.f};

    int n = 0;
    for (; n + 3 < cnt; n += 4) {
        int j0 = slist[wid][n],     j1 = slist[wid][n + 1];
        int j2 = slist[wid][n + 2], j3 = slist[wid][n + 3];
        uint4 va = xwh[j0 * 32 + lane];
        uint4 vb = xwh[j1 * 32 + lane];
        uint4 vc = xwh[j2 * 32 + lane];
        uint4 vd = xwh[j3 * 32 + lane];
        const __half2* ha = reinterpret_cast<const __half2*>(&va);
        const __half2* hb = reinterpret_cast<const __half2*>(&vb);
        const __half2* hc = reinterpret_cast<const __half2*>(&vc);
        const __half2* hd = reinterpret_cast<const __half2*>(&vd);
        #pragma unroll
        for (int i = 0; i < 4; i++) {
            __half2 s01 = __hadd2(ha[i], hb[i]);
            __half2 s23 = __hadd2(hc[i], hd[i]);
            __half2 s   = __hadd2(s01, s23);
            float2 f = __half22float2(s);
            acc[2 * i]     += f.x;
            acc[2 * i + 1] += f.y;
        }
    }
    if (n + 1 < cnt) {
        int j0 = slist[wid][n], j1 = slist[wid][n + 1];
        uint4 va = xwh[j0 * 32 + lane];
        uint4 vb = xwh[j1 * 32 + lane];
        const __half2* ha = reinterpret_cast<const __half2*>(&va);
        const __half2* hb = reinterpret_cast<const __half2*>(&vb);
        #pragma unroll
        for (int i = 0; i < 4; i++) {
            __half2 s = __hadd2(ha[i], hb[i]);
            float2 f = __half22float2(s);
            acc[2 * i]     += f.x;
            acc[2 * i + 1] += f.y;
        }
        n += 2;
    }
    if (n < cnt) {
        uint4 v = xwh[slist[wid][n] * 32 + lane];
        add8(acc, v);
    }

    float dv = rsqrtf((float)deg);
    float4 r0 = make_float4(dv * acc[0], dv * acc[1], dv * acc[2], dv * acc[3]);
    float4 r1 = make_float4(dv * acc[4], dv * acc[5], dv * acc[6], dv * acc[7]);
    float4* out4 = reinterpret_cast<float4*>(out + row * OUT_CH);
    out4[lane * 2]     = r0;
    out4[lane * 2 + 1] = r1;
}

// ---------------------------------------------------------------------------
// Launch: fork-join graph.
//   stream 0 : init -> scatter ----\
//   stream B : gemm (x,w only) -----+--> scale -> aggregate
// ---------------------------------------------------------------------------
extern "C" void kernel_launch(void* const* d_in, const int* in_sizes, int n_in,
                              void* d_out, int out_size) {
    const float* x  = (const float*)d_in[0];   // [10000, 256] f32
    const float* w  = (const float*)d_in[1];   // [256, 256]   f32
    const int*   ei = (const int*)d_in[2];     // [2, 320000]  i32
    float* out = (float*)d_out;                // [10000, 256] f32

    cudaStream_t sB;
    cudaEvent_t evRoot, evGemm;
    cudaStreamCreateWithFlags(&sB, cudaStreamNonBlocking);
    cudaEventCreateWithFlags(&evRoot, cudaEventDisableTiming);
    cudaEventCreateWithFlags(&evGemm, cudaEventDisableTiming);

    cudaEventRecord(evRoot, 0);
    cudaStreamWaitEvent(sB, evRoot, 0);

    dim3 ggrid(OUT_CH / BN, (N_NODES + BM - 1) / BM);   // (4, 79) = 316 blocks
    k_gemm<<<ggrid, 256, 0, sB>>>(x, w);
    cudaEventRecord(evGemm, sB);

    k_init<<<INIT_BLOCKS, INIT_THREADS>>>();
    k_scatter<<<(N_EDGES + 255) / 256, 256>>>(ei);

    cudaStreamWaitEvent(0, evGemm, 0);
    k_scale<<<1250, 256>>>();
    k_aggregate<<<N_NODES / AGG_WARPS, 256>>>(out);
}